// round 16
// baseline (speedup 1.0000x reference)
#include <cuda_runtime.h>
#include <cuda_bf16.h>
#include <math.h>
#include <stdint.h>

#define N_NODES 10000
#define N_EDGES 320000
#define N_GRAPHS 64

// ============================ device scratch =================================
__device__ __align__(16) float g_h1[N_NODES * 128];
__device__ __align__(16) float g_h2[N_NODES * 256];
__device__ __align__(16) float g_gi[N_NODES * 768];
__device__ __align__(16) float g_gh[N_NODES * 768];
__device__ int   g_rowptr[N_NODES + 1];
__device__ int   g_cnt[N_NODES];
__device__ int   g_cursor[N_NODES];
__device__ int   g_csr_src[N_EDGES];
__device__ unsigned g_pool[N_GRAPHS * 256];
__device__ int   g_e64, g_b64;
__device__ int   g_poolctr;
__device__ __align__(16) __nv_bfloat16 g_hh[N_NODES * 256], g_hl[N_NODES * 256];
__device__ __align__(16) __nv_bfloat16 g_ah[N_NODES * 256], g_al[N_NODES * 256];
__device__ __align__(16) __nv_bfloat16 g_w1uh[3*128*128], g_w1ul[3*128*128];
__device__ __align__(16) __nv_bfloat16 g_w2uh[3*256*256], g_w2ul[3*256*256];
__device__ __align__(16) __nv_bfloat16 g_i1h[384*128],  g_i1l[384*128];
__device__ __align__(16) __nv_bfloat16 g_r1h[384*128],  g_r1l[384*128];
__device__ __align__(16) __nv_bfloat16 g_i2h[768*256],  g_i2l[768*256];
__device__ __align__(16) __nv_bfloat16 g_r2h[768*256],  g_r2l[768*256];
__device__ __align__(16) __nv_bfloat16 g_v1h[3*384*128], g_v1l[3*384*128];
__device__ __align__(16) __nv_bfloat16 g_v2h[3*768*256], g_v2l[3*768*256];

// ============================ helpers ========================================
__device__ __forceinline__ unsigned f2ord(float f) {
    unsigned u = __float_as_uint(f);
    return (u & 0x80000000u) ? ~u : (u | 0x80000000u);
}
__device__ __forceinline__ float ord2f(unsigned u) {
    u = (u & 0x80000000u) ? (u & 0x7fffffffu) : ~u;
    return __uint_as_float(u);
}
__device__ __forceinline__ int load_idx(const void* p, long i, int is64) {
    return is64 ? (int)((const long long*)p)[i] : ((const int*)p)[i];
}
__device__ __forceinline__ void split1(float f, __nv_bfloat16& h, __nv_bfloat16& l) {
    h = __float2bfloat16(f);
    l = __float2bfloat16(f - __bfloat162float(h));
}

// ============================ prep ===========================================
__global__ void prep_kernel(const void* edge, const void* batch,
                            int* cnt, unsigned* pool) {
    int b = blockIdx.x, tid = threadIdx.x;
    int i = b * 256 + tid;
    if (i < N_NODES) cnt[i] = 0;
    if (i < N_GRAPHS * 256) pool[i] = f2ord(-3.402823466e38f);
    if (b == 0 && tid == 0) g_poolctr = 0;
    if (b == 64) {
        __shared__ int eo, bo;
        if (tid == 0) { eo = 0; bo = 0; }
        __syncthreads();
        const unsigned* we = (const unsigned*)edge;
        const unsigned* wb = (const unsigned*)batch;
        long ie = (long)tid * ((2L * N_EDGES) / 256);
        if (we[2 * ie + 1] != 0u) atomicOr(&eo, 1);
        long jb = (long)tid * (N_NODES / 256);
        if (wb[2 * jb + 1] != 0u) atomicOr(&bo, 1);
        __syncthreads();
        if (tid == 0) { g_e64 = !eo; g_b64 = !bo; }
    }
}

// =================== fused: hi/lo splits (z=0..6) + edge count (z=7) =========
struct SJob { const float* in; __nv_bfloat16* hi; __nv_bfloat16* lo; int n4; };
struct SJobs { SJob j[7]; };
__global__ void split_count_kernel(SJobs js, const void* edge, int* cnt) {
    if (blockIdx.z == 7) {
        int e = blockIdx.x * 256 + threadIdx.x;
        if (e < N_EDGES)
            atomicAdd(&cnt[load_idx(edge, (long)N_EDGES + e, g_e64)], 1);
        return;
    }
    SJob jb = js.j[blockIdx.z];
    int i = blockIdx.x * 256 + threadIdx.x;
    if (i >= jb.n4) return;
    float4 v = ((const float4*)jb.in)[i];
    __nv_bfloat16 h0, h1, h2, h3, l0, l1, l2, l3;
    split1(v.x, h0, l0); split1(v.y, h1, l1); split1(v.z, h2, l2); split1(v.w, h3, l3);
    ((__nv_bfloat162*)jb.hi)[2*i]   = __halves2bfloat162(h0, h1);
    ((__nv_bfloat162*)jb.hi)[2*i+1] = __halves2bfloat162(h2, h3);
    ((__nv_bfloat162*)jb.lo)[2*i]   = __halves2bfloat162(l0, l1);
    ((__nv_bfloat162*)jb.lo)[2*i+1] = __halves2bfloat162(l2, l3);
}

// ============================ CSR scan + fill ================================
__global__ void scan_kernel(const int* __restrict__ cnt, int* __restrict__ rowptr,
                            int* __restrict__ cursor, int n) {
    __shared__ int wsum[32];
    int tid = threadIdx.x, lane = tid & 31, wid = tid >> 5;
    int base = tid * 10;
    int v[10]; int s = 0;
    #pragma unroll
    for (int q = 0; q < 10; q++) {
        int i = base + q;
        int x = (i < n) ? cnt[i] : 0;
        s += x; v[q] = s;
    }
    int incl = s;
    #pragma unroll
    for (int o = 1; o < 32; o <<= 1) {
        int y = __shfl_up_sync(0xffffffffu, incl, o);
        if (lane >= o) incl += y;
    }
    if (lane == 31) wsum[wid] = incl;
    __syncthreads();
    if (wid == 0) {
        int t = wsum[lane];
        #pragma unroll
        for (int o = 1; o < 32; o <<= 1) {
            int y = __shfl_up_sync(0xffffffffu, t, o);
            if (lane >= o) t += y;
        }
        wsum[lane] = t;
    }
    __syncthreads();
    int excl = incl - s + (wid ? wsum[wid - 1] : 0);
    #pragma unroll
    for (int q = 0; q < 10; q++) {
        int i = base + q;
        if (i < n) {
            rowptr[i + 1] = excl + v[q];
            cursor[i] = excl + (q ? v[q - 1] : 0);
        }
    }
    if (tid == 0) rowptr[0] = 0;
}
__global__ void fill_kernel(const void* edge, int* cursor, int* csr_src) {
    int e = blockIdx.x * blockDim.x + threadIdx.x;
    if (e >= N_EDGES) return;
    int is64 = g_e64;
    int src = load_idx(edge, e, is64);
    int dst = load_idx(edge, (long)N_EDGES + e, is64);
    csr_src[atomicAdd(&cursor[dst], 1)] = src;
}

// ============================ HMMA GEMM core (128x128, 8 warps 32x64) ========
// 3 passes per 64-K block: (Ahi,Bhi), (Alo,Bhi), (Ahi,Blo) — Bhi/Ahi loaded
// ONCE per block into parity-indexed slots, Alo/Blo streamed.
// smem slots: 0=Ahi_even 1=Ahi_odd 2=Alo | 3=Bhi_even 4=Bhi_odd 5=Blo
struct GOp {
    const __nv_bfloat16 *Ah, *Al, *Bh, *Bl;
    const float* bias;
    float* C;
    __nv_bfloat16 *Chi, *Clo;
};
struct GTriple { GOp o[3]; };
#define TILE128 (128 * 72)
#define GEMM_SMEM (3 * 2 * TILE128 * 2)

__device__ __forceinline__ void ldsm_x4(uint32_t* r, uint32_t addr) {
    asm volatile("ldmatrix.sync.aligned.m8n8.x4.shared.b16 {%0,%1,%2,%3}, [%4];"
        : "=r"(r[0]), "=r"(r[1]), "=r"(r[2]), "=r"(r[3]) : "r"(addr));
}
__device__ __forceinline__ void mma_16816(float* d, const uint32_t* a,
                                          uint32_t b0, uint32_t b1) {
    asm volatile("mma.sync.aligned.m16n8k16.row.col.f32.bf16.bf16.f32 "
        "{%0,%1,%2,%3}, {%4,%5,%6,%7}, {%8,%9}, {%0,%1,%2,%3};"
        : "+f"(d[0]), "+f"(d[1]), "+f"(d[2]), "+f"(d[3])
        : "r"(a[0]), "r"(a[1]), "r"(a[2]), "r"(a[3]), "r"(b0), "r"(b1));
}
__device__ __forceinline__ void cp16(uint32_t dst, const void* src, bool pred) {
    int sz = pred ? 16 : 0;
    asm volatile("cp.async.cg.shared.global [%0], [%1], 16, %2;"
        :: "r"(dst), "l"(src), "r"(sz) : "memory");
}
__device__ __forceinline__ void gemm_issue(
    const GOp& o, int c, int nc, int tid, int row0, int col0,
    int Nrows, int K, uint32_t smu)
{
    if (c < nc) {
        int k0i = c / 3, p = c - k0i * 3;
        int k0 = k0i << 6;
        int par = k0i & 1;
        if (p == 0) {
            uint32_t bA = smu + (uint32_t)(par * TILE128) * 2;
            uint32_t bB = smu + (uint32_t)((3 + par) * TILE128) * 2;
            #pragma unroll
            for (int q = 0; q < 4; q++) {
                int idx = q * 256 + tid;
                int row = idx >> 3, seg = (idx & 7) << 3;
                int gr = row0 + row;
                long grc = (gr < Nrows) ? gr : 0;
                cp16(bA + (uint32_t)(row * 72 + seg) * 2,
                     o.Ah + grc * K + k0 + seg, gr < Nrows);
                cp16(bB + (uint32_t)(row * 72 + seg) * 2,
                     o.Bh + (long)(col0 + row) * K + k0 + seg, true);
            }
        } else if (p == 1) {
            uint32_t bA = smu + (uint32_t)(2 * TILE128) * 2;
            #pragma unroll
            for (int q = 0; q < 4; q++) {
                int idx = q * 256 + tid;
                int row = idx >> 3, seg = (idx & 7) << 3;
                int gr = row0 + row;
                long grc = (gr < Nrows) ? gr : 0;
                cp16(bA + (uint32_t)(row * 72 + seg) * 2,
                     o.Al + grc * K + k0 + seg, gr < Nrows);
            }
        } else {
            uint32_t bB = smu + (uint32_t)(5 * TILE128) * 2;
            #pragma unroll
            for (int q = 0; q < 4; q++) {
                int idx = q * 256 + tid;
                int row = idx >> 3, seg = (idx & 7) << 3;
                cp16(bB + (uint32_t)(row * 72 + seg) * 2,
                     o.Bl + (long)(col0 + row) * K + k0 + seg, true);
            }
        }
    }
    asm volatile("cp.async.commit_group;" ::: "memory");
}

__device__ void gemm_body256(const GOp& o, int row0, int col0,
                             int Nrows, int K, int Ncols)
{
    extern __shared__ __nv_bfloat16 smg[];
    uint32_t smu = (uint32_t)__cvta_generic_to_shared(smg);
    int tid = threadIdx.x, lane = tid & 31, wid = tid >> 5;
    int wm = (wid & 3) * 32, wn = (wid >> 2) * 64;

    float acc[2][8][4];
    #pragma unroll
    for (int i = 0; i < 2; i++)
        #pragma unroll
        for (int j = 0; j < 8; j++)
            #pragma unroll
            for (int q = 0; q < 4; q++) acc[i][j][q] = 0.f;

    int nc = 3 * (K >> 6);
    gemm_issue(o, 0, nc, tid, row0, col0, Nrows, K, smu);
    gemm_issue(o, 1, nc, tid, row0, col0, Nrows, K, smu);

    for (int c = 0; c < nc; c++) {
        asm volatile("cp.async.wait_group 1;" ::: "memory");
        __syncthreads();
        gemm_issue(o, c + 2, nc, tid, row0, col0, Nrows, K, smu);

        int k0i = c / 3, p = c - k0i * 3;
        int par = k0i & 1;
        int slotA = (p == 1) ? 2 : par;
        int slotB = (p == 2) ? 5 : (3 + par);
        uint32_t bA = smu + (uint32_t)(slotA * TILE128) * 2;
        uint32_t bB = smu + (uint32_t)(slotB * TILE128) * 2;
        #pragma unroll
        for (int ks = 0; ks < 4; ks++) {
            uint32_t af[2][4], bf[4][4];
            #pragma unroll
            for (int ti = 0; ti < 2; ti++) {
                int row = wm + ti * 16 + (lane & 15);
                int col = ks * 16 + (lane >> 4) * 8;
                ldsm_x4(af[ti], bA + (uint32_t)(row * 72 + col) * 2);
            }
            #pragma unroll
            for (int g = 0; g < 4; g++) {
                int row = wn + g * 16 + (lane & 7) + ((lane >> 4) << 3);
                int col = ks * 16 + ((lane >> 3) & 1) * 8;
                ldsm_x4(bf[g], bB + (uint32_t)(row * 72 + col) * 2);
            }
            #pragma unroll
            for (int ti = 0; ti < 2; ti++)
                #pragma unroll
                for (int g = 0; g < 4; g++) {
                    mma_16816(acc[ti][g*2],     af[ti], bf[g][0], bf[g][1]);
                    mma_16816(acc[ti][g*2 + 1], af[ti], bf[g][2], bf[g][3]);
                }
        }
    }

    #pragma unroll
    for (int ti = 0; ti < 2; ti++) {
        int rb = row0 + wm + ti * 16 + (lane >> 2);
        #pragma unroll
        for (int g = 0; g < 8; g++) {
            int col = col0 + wn + g * 8 + (lane & 3) * 2;
            float bx = 0.f, by = 0.f;
            if (o.bias) { bx = o.bias[col]; by = o.bias[col + 1]; }
            float v0 = acc[ti][g][0] + bx, v1 = acc[ti][g][1] + by;
            float v2 = acc[ti][g][2] + bx, v3 = acc[ti][g][3] + by;
            if (o.Chi) {
                __nv_bfloat16 h0, h1, l0, l1;
                if (rb < Nrows) {
                    split1(v0, h0, l0); split1(v1, h1, l1);
                    *(__nv_bfloat162*)&o.Chi[(long)rb * Ncols + col] = __halves2bfloat162(h0, h1);
                    *(__nv_bfloat162*)&o.Clo[(long)rb * Ncols + col] = __halves2bfloat162(l0, l1);
                }
                if (rb + 8 < Nrows) {
                    split1(v2, h0, l0); split1(v3, h1, l1);
                    *(__nv_bfloat162*)&o.Chi[(long)(rb+8) * Ncols + col] = __halves2bfloat162(h0, h1);
                    *(__nv_bfloat162*)&o.Clo[(long)(rb+8) * Ncols + col] = __halves2bfloat162(l0, l1);
                }
            } else {
                if (rb < Nrows)
                    *(float2*)&o.C[(long)rb * Ncols + col] = make_float2(v0, v1);
                if (rb + 8 < Nrows)
                    *(float2*)&o.C[(long)(rb + 8) * Ncols + col] = make_float2(v2, v3);
            }
        }
    }
}

__global__ __launch_bounds__(256, 2) void gemm256_kernel(
    GTriple t, int Nrows, int K, int Ncols)
{
    gemm_body256(t.o[blockIdx.z], blockIdx.y * 128, blockIdx.x * 128, Nrows, K, Ncols);
}

// merged V1+V2 precompute: grid dim3(2,6,6); z<3 -> V1 (1x3 tiles), z>=3 -> V2
__global__ __launch_bounds__(256, 2) void gemm_v_kernel(GTriple t1, GTriple t2)
{
    if (blockIdx.z < 3) {
        if (blockIdx.x >= 1 || blockIdx.y >= 3) return;
        gemm_body256(t1.o[blockIdx.z], blockIdx.y * 128, blockIdx.x * 128, 384, 128, 128);
    } else {
        gemm_body256(t2.o[blockIdx.z - 3], blockIdx.y * 128, blockIdx.x * 128, 768, 256, 256);
    }
}

// ============================ aggregation (fp32 gather, fused split) =========
__global__ void aggregate_split_kernel(const float4* __restrict__ h4,
                                       __nv_bfloat16* __restrict__ ahi,
                                       __nv_bfloat16* __restrict__ alo,
                                       const int* __restrict__ rowptr,
                                       const int* __restrict__ csr, int C4)
{
    int n = blockIdx.x * blockDim.y + threadIdx.y;
    if (n >= N_NODES) return;
    int f = threadIdx.x;
    int beg = rowptr[n], end = rowptr[n + 1];
    float4 a0 = make_float4(0.f,0.f,0.f,0.f), a1 = a0, a2 = a0, a3 = a0;
    int j = beg;
    for (; j + 4 <= end; j += 4) {
        int s0 = csr[j], s1 = csr[j+1], s2 = csr[j+2], s3 = csr[j+3];
        float4 v0 = h4[(long)s0 * C4 + f];
        float4 v1 = h4[(long)s1 * C4 + f];
        float4 v2 = h4[(long)s2 * C4 + f];
        float4 v3 = h4[(long)s3 * C4 + f];
        a0.x += v0.x; a0.y += v0.y; a0.z += v0.z; a0.w += v0.w;
        a1.x += v1.x; a1.y += v1.y; a1.z += v1.z; a1.w += v1.w;
        a2.x += v2.x; a2.y += v2.y; a2.z += v2.z; a2.w += v2.w;
        a3.x += v3.x; a3.y += v3.y; a3.z += v3.z; a3.w += v3.w;
    }
    for (; j < end; j++) {
        int s = csr[j];
        float4 v = h4[(long)s * C4 + f];
        a0.x += v.x; a0.y += v.y; a0.z += v.z; a0.w += v.w;
    }
    float4 acc;
    acc.x = (a0.x + a1.x) + (a2.x + a3.x);
    acc.y = (a0.y + a1.y) + (a2.y + a3.y);
    acc.z = (a0.z + a1.z) + (a2.z + a3.z);
    acc.w = (a0.w + a1.w) + (a2.w + a3.w);
    long o = ((long)n * C4 + f) * 2;
    __nv_bfloat16 h0,h1,h2,h3,l0,l1,l2,l3;
    split1(acc.x, h0, l0); split1(acc.y, h1, l1);
    split1(acc.z, h2, l2); split1(acc.w, h3, l3);
    ((__nv_bfloat162*)ahi)[o]   = __halves2bfloat162(h0, h1);
    ((__nv_bfloat162*)ahi)[o+1] = __halves2bfloat162(h2, h3);
    ((__nv_bfloat162*)alo)[o]   = __halves2bfloat162(l0, l1);
    ((__nv_bfloat162*)alo)[o+1] = __halves2bfloat162(l2, l3);
}

// ============================ GRU (float4, fused split) ======================
__global__ void gru_split_kernel(const float4* __restrict__ gi4, const float4* __restrict__ gh4,
                                 const float4* __restrict__ h4, float4* __restrict__ hout4,
                                 __nv_bfloat16* __restrict__ hhi, __nv_bfloat16* __restrict__ hlo,
                                 int C)
{
    int i = blockIdx.x * blockDim.x + threadIdx.x;
    int C4 = C >> 2;
    if (i >= N_NODES * C4) return;
    int n = i / C4, f4 = i % C4;
    const float4* gir = gi4 + (long)n * 3 * C4;
    const float4* ghr = gh4 + (long)n * 3 * C4;
    float4 ir = gir[f4], iz = gir[C4 + f4], in_ = gir[2 * C4 + f4];
    float4 hr = ghr[f4], hz = ghr[C4 + f4], hn  = ghr[2 * C4 + f4];
    float4 hv = h4[i];
    float o[4];
    {
        float r0 = 1.f / (1.f + expf(-(ir.x + hr.x)));
        float z0 = 1.f / (1.f + expf(-(iz.x + hz.x)));
        o[0] = (1.f - z0) * tanhf(in_.x + r0 * hn.x) + z0 * hv.x;
        float r1 = 1.f / (1.f + expf(-(ir.y + hr.y)));
        float z1 = 1.f / (1.f + expf(-(iz.y + hz.y)));
        o[1] = (1.f - z1) * tanhf(in_.y + r1 * hn.y) + z1 * hv.y;
        float r2 = 1.f / (1.f + expf(-(ir.z + hr.z)));
        float z2 = 1.f / (1.f + expf(-(iz.z + hz.z)));
        o[2] = (1.f - z2) * tanhf(in_.z + r2 * hn.z) + z2 * hv.z;
        float r3 = 1.f / (1.f + expf(-(ir.w + hr.w)));
        float z3 = 1.f / (1.f + expf(-(iz.w + hz.w)));
        o[3] = (1.f - z3) * tanhf(in_.w + r3 * hn.w) + z3 * hv.w;
    }
    hout4[i] = make_float4(o[0], o[1], o[2], o[3]);
    __nv_bfloat16 bh0,bh1,bh2,bh3,bl0,bl1,bl2,bl3;
    split1(o[0], bh0, bl0); split1(o[1], bh1, bl1);
    split1(o[2], bh2, bl2); split1(o[3], bh3, bl3);
    ((__nv_bfloat162*)hhi)[2*i]   = __halves2bfloat162(bh0, bh1);
    ((__nv_bfloat162*)hhi)[2*i+1] = __halves2bfloat162(bh2, bh3);
    ((__nv_bfloat162*)hlo)[2*i]   = __halves2bfloat162(bl0, bl1);
    ((__nv_bfloat162*)hlo)[2*i+1] = __halves2bfloat162(bl2, bl3);
}

// Final stage-1 GRU: fuses relu + pad 128->256 (writes 256-wide h2 + hi/lo).
__global__ void gru_pad_relu_split_kernel(
    const float4* __restrict__ gi4, const float4* __restrict__ gh4,
    const float4* __restrict__ h4, float4* __restrict__ h2_4,
    __nv_bfloat16* __restrict__ hhi, __nv_bfloat16* __restrict__ hlo)
{
    int i = blockIdx.x * blockDim.x + threadIdx.x;        // over N_NODES*64
    if (i >= N_NODES * 64) return;
    int n = i >> 6, f4 = i & 63;
    float o[4] = {0.f, 0.f, 0.f, 0.f};
    if (f4 < 32) {
        const float4* gir = gi4 + (long)n * 96;
        const float4* ghr = gh4 + (long)n * 96;
        float4 ir = gir[f4], iz = gir[32 + f4], in_ = gir[64 + f4];
        float4 hr = ghr[f4], hz = ghr[32 + f4], hn  = ghr[64 + f4];
        float4 hv = h4[n * 32 + f4];
        float r0 = 1.f / (1.f + expf(-(ir.x + hr.x)));
        float z0 = 1.f / (1.f + expf(-(iz.x + hz.x)));
        o[0] = fmaxf((1.f - z0) * tanhf(in_.x + r0 * hn.x) + z0 * hv.x, 0.f);
        float r1 = 1.f / (1.f + expf(-(ir.y + hr.y)));
        float z1 = 1.f / (1.f + expf(-(iz.y + hz.y)));
        o[1] = fmaxf((1.f - z1) * tanhf(in_.y + r1 * hn.y) + z1 * hv.y, 0.f);
        float r2 = 1.f / (1.f + expf(-(ir.z + hr.z)));
        float z2 = 1.f / (1.f + expf(-(iz.z + hz.z)));
        o[2] = fmaxf((1.f - z2) * tanhf(in_.z + r2 * hn.z) + z2 * hv.z, 0.f);
        float r3 = 1.f / (1.f + expf(-(ir.w + hr.w)));
        float z3 = 1.f / (1.f + expf(-(iz.w + hz.w)));
        o[3] = fmaxf((1.f - z3) * tanhf(in_.w + r3 * hn.w) + z3 * hv.w, 0.f);
    }
    h2_4[i] = make_float4(o[0], o[1], o[2], o[3]);
    __nv_bfloat16 bh0,bh1,bh2,bh3,bl0,bl1,bl2,bl3;
    split1(o[0], bh0, bl0); split1(o[1], bh1, bl1);
    split1(o[2], bh2, bl2); split1(o[3], bh3, bl3);
    ((__nv_bfloat162*)hhi)[2*i]   = __halves2bfloat162(bh0, bh1);
    ((__nv_bfloat162*)hhi)[2*i+1] = __halves2bfloat162(bh2, bh3);
    ((__nv_bfloat162*)hlo)[2*i]   = __halves2bfloat162(bl0, bl1);
    ((__nv_bfloat162*)hlo)[2*i+1] = __halves2bfloat162(bl2, bl3);
}

// ============================ pooling + FC (fused) ===========================
// Hierarchical segment-max; the LAST block (atomic counter) also runs the FC.
__global__ void pool_fc_kernel(const float* __restrict__ h, const void* batch,
                               unsigned* __restrict__ pool,
                               const float* __restrict__ w, const float* __restrict__ b,
                               float* __restrict__ out, int nblocks) {
    int f = threadIdx.x;                  // 0..255
    int n0 = blockIdx.x * 64;
    int b64 = g_b64;
    int gcur = -1;
    float m = -3.402823466e38f;
    #pragma unroll 4
    for (int k = 0; k < 64; k++) {
        int n = n0 + k;
        if (n >= N_NODES) break;
        int g = load_idx(batch, n, b64);
        if (g != gcur) {
            if (gcur >= 0) atomicMax(&pool[gcur * 256 + f], f2ord(m));
            gcur = g;
            m = -3.402823466e38f;
        }
        m = fmaxf(m, h[(long)n * 256 + f]);
    }
    if (gcur >= 0) atomicMax(&pool[gcur * 256 + f], f2ord(m));

    // last-block-does-FC (strided over all 384 outputs)
    __shared__ int amLast;
    __threadfence();
    __syncthreads();
    if (f == 0) amLast = (atomicAdd(&g_poolctr, 1) == nblocks - 1);
    __syncthreads();
    if (!amLast) return;
    __threadfence();   // ensure all pool atomics visible
    for (int t = f; t < N_GRAPHS * 6; t += 256) {
        int g = t / 6, j = t % 6;
        float s = b[j];
        #pragma unroll 8
        for (int k = 0; k < 256; k++)
            s += ord2f(pool[g * 256 + k]) * w[j * 256 + k];
        out[t] = s;
    }
}

// ============================ launch =========================================
static inline GOp mkop(const __nv_bfloat16* Ah, const __nv_bfloat16* Al,
                       const __nv_bfloat16* Bh, const __nv_bfloat16* Bl,
                       const float* bias, float* C,
                       __nv_bfloat16* Chi = nullptr, __nv_bfloat16* Clo = nullptr) {
    GOp o; o.Ah = Ah; o.Al = Al; o.Bh = Bh; o.Bl = Bl;
    o.bias = bias; o.C = C; o.Chi = Chi; o.Clo = Clo; return o;
}

extern "C" void kernel_launch(void* const* d_in, const int* in_sizes, int n_in,
                              void* d_out, int out_size)
{
    const float* x       = (const float*)d_in[0];
    const void*  edge    = d_in[1];
    const void*  batch   = d_in[2];
    const float* w1      = (const float*)d_in[3];
    const float* g1_wih  = (const float*)d_in[4];
    const float* g1_whh  = (const float*)d_in[5];
    const float* g1_bih  = (const float*)d_in[6];
    const float* g1_bhh  = (const float*)d_in[7];
    const float* w2      = (const float*)d_in[8];
    const float* g2_wih  = (const float*)d_in[9];
    const float* g2_whh  = (const float*)d_in[10];
    const float* g2_bih  = (const float*)d_in[11];
    const float* g2_bhh  = (const float*)d_in[12];
    const float* fc_w    = (const float*)d_in[13];
    const float* fc_b    = (const float*)d_in[14];

    cudaFuncSetAttribute(gemm256_kernel, cudaFuncAttributeMaxDynamicSharedMemorySize,
                         GEMM_SMEM);
    cudaFuncSetAttribute(gemm_v_kernel, cudaFuncAttributeMaxDynamicSharedMemorySize,
                         GEMM_SMEM);

    static cudaStream_t s1 = nullptr;
    static cudaEvent_t evF = nullptr, evJ = nullptr;
    if (!s1) {
        cudaStreamCreateWithFlags(&s1, cudaStreamNonBlocking);
        cudaEventCreateWithFlags(&evF, cudaEventDisableTiming);
        cudaEventCreateWithFlags(&evJ, cudaEventDisableTiming);
    }

    float *h1, *h2, *gi, *gh;
    int *rowptr, *cnt, *cursor, *csr;
    unsigned* pool;
    __nv_bfloat16 *hh, *hl, *ah, *al;
    __nv_bfloat16 *w1uh, *w1ul, *w2uh, *w2ul;
    __nv_bfloat16 *i1h, *i1l, *r1h, *r1l, *i2h, *i2l, *r2h, *r2l;
    __nv_bfloat16 *v1h, *v1l, *v2h, *v2l;
    cudaGetSymbolAddress((void**)&h1, g_h1);   cudaGetSymbolAddress((void**)&h2, g_h2);
    cudaGetSymbolAddress((void**)&gi, g_gi);   cudaGetSymbolAddress((void**)&gh, g_gh);
    cudaGetSymbolAddress((void**)&rowptr, g_rowptr); cudaGetSymbolAddress((void**)&cnt, g_cnt);
    cudaGetSymbolAddress((void**)&cursor, g_cursor); cudaGetSymbolAddress((void**)&csr, g_csr_src);
    cudaGetSymbolAddress((void**)&pool, g_pool);
    cudaGetSymbolAddress((void**)&hh, g_hh);   cudaGetSymbolAddress((void**)&hl, g_hl);
    cudaGetSymbolAddress((void**)&ah, g_ah);   cudaGetSymbolAddress((void**)&al, g_al);
    cudaGetSymbolAddress((void**)&w1uh, g_w1uh); cudaGetSymbolAddress((void**)&w1ul, g_w1ul);
    cudaGetSymbolAddress((void**)&w2uh, g_w2uh); cudaGetSymbolAddress((void**)&w2ul, g_w2ul);
    cudaGetSymbolAddress((void**)&i1h, g_i1h); cudaGetSymbolAddress((void**)&i1l, g_i1l);
    cudaGetSymbolAddress((void**)&r1h, g_r1h); cudaGetSymbolAddress((void**)&r1l, g_r1l);
    cudaGetSymbolAddress((void**)&i2h, g_i2h); cudaGetSymbolAddress((void**)&i2l, g_i2l);
    cudaGetSymbolAddress((void**)&r2h, g_r2h); cudaGetSymbolAddress((void**)&r2l, g_r2l);
    cudaGetSymbolAddress((void**)&v1h, g_v1h); cudaGetSymbolAddress((void**)&v1l, g_v1l);
    cudaGetSymbolAddress((void**)&v2h, g_v2h); cudaGetSymbolAddress((void**)&v2l, g_v2l);

    // ---- prologue ----
    prep_kernel<<<65, 256>>>(edge, batch, cnt, pool);

    SJobs js;
    js.j[0] = { x,      hh,   hl,   N_NODES*128/4 };
    js.j[1] = { w1,     w1uh, w1ul, 3*128*128/4 };
    js.j[2] = { w2,     w2uh, w2ul, 3*256*256/4 };
    js.j[3] = { g1_wih, i1h,  i1l,  384*128/4 };
    js.j[4] = { g1_whh, r1h,  r1l,  384*128/4 };
    js.j[5] = { g2_wih, i2h,  i2l,  768*256/4 };
    js.j[6] = { g2_whh, r2h,  r2l,  768*256/4 };
    split_count_kernel<<<dim3(1250, 1, 8), 256>>>(js, edge, cnt);

    // fork: side stream does V precompute (merged) + layer-0 gh
    cudaEventRecord(evF, 0);
    cudaStreamWaitEvent(s1, evF, 0);
    {
        GTriple t1, t2;
        for (int q = 0; q < 3; q++) {
            t1.o[q] = mkop(i1h, i1l, w1uh + (long)q*128*128, w1ul + (long)q*128*128,
                           nullptr, nullptr, v1h + (long)q*384*128, v1l + (long)q*384*128);
            t2.o[q] = mkop(i2h, i2l, w2uh + (long)q*256*256, w2ul + (long)q*256*256,
                           nullptr, nullptr, v2h + (long)q*768*256, v2l + (long)q*768*256);
        }
        gemm_v_kernel<<<dim3(2, 6, 6), 256, GEMM_SMEM, s1>>>(t1, t2);
    }
    {
        GTriple t;
        t.o[0] = mkop(hh, hl, r1h, r1l, g1_bhh, gh);
        t.o[1] = t.o[0]; t.o[2] = t.o[0];
        gemm256_kernel<<<dim3(3, 79, 1), 256, GEMM_SMEM, s1>>>(t, N_NODES, 128, 384);
    }

    // main stream: CSR build + layer-0 aggregation (fp32 gather of x)
    scan_kernel<<<1, 1024>>>(cnt, rowptr, cursor, N_NODES);
    fill_kernel<<<(N_EDGES + 255) / 256, 256>>>(edge, cursor, csr);
    aggregate_split_kernel<<<1250, dim3(32, 8)>>>((const float4*)x, ah, al, rowptr, csr, 32);

    // ---- stage 1: C = 128 ----
    for (int i = 0; i < 3; i++) {
        const float* h = (i == 0) ? x : h1;
        if (i > 0) {
            cudaEventRecord(evF, 0);
            cudaStreamWaitEvent(s1, evF, 0);
            GTriple tg;
            tg.o[0] = mkop(hh, hl, r1h, r1l, g1_bhh, gh);
            tg.o[1] = tg.o[0]; tg.o[2] = tg.o[0];
            gemm256_kernel<<<dim3(3, 79, 1), 256, GEMM_SMEM, s1>>>(tg, N_NODES, 128, 384);
            aggregate_split_kernel<<<1250, dim3(32, 8)>>>((const float4*)h, ah, al,
                                                          rowptr, csr, 32);
        } else {
            // layer 0 gi needs V1 from s1 — join before gi
            cudaEventRecord(evJ, s1);
            cudaStreamWaitEvent(0, evJ, 0);
        }

        GTriple t;
        t.o[0] = mkop(ah, al, v1h + (long)i*384*128, v1l + (long)i*384*128, g1_bih, gi);
        t.o[1] = t.o[0]; t.o[2] = t.o[0];
        gemm256_kernel<<<dim3(3, 79, 1), 256, GEMM_SMEM>>>(t, N_NODES, 128, 384);

        // join gh before gru (gi itself doesn't need gh)
        if (i > 0) {
            cudaEventRecord(evJ, s1);
            cudaStreamWaitEvent(0, evJ, 0);
        }
        if (i < 2) {
            gru_split_kernel<<<(N_NODES*32 + 255) / 256, 256>>>(
                (const float4*)gi, (const float4*)gh, (const float4*)h, (float4*)h1,
                hh, hl, 128);
        } else {
            gru_pad_relu_split_kernel<<<(N_NODES*64 + 255) / 256, 256>>>(
                (const float4*)gi, (const float4*)gh, (const float4*)h, (float4*)h2,
                hh, hl);
        }
    }

    // ---- stage 2: C = 256 ----
    for (int i = 0; i < 3; i++) {
        cudaEventRecord(evF, 0);
        cudaStreamWaitEvent(s1, evF, 0);
        GTriple tg;
        tg.o[0] = mkop(hh, hl, r2h, r2l, g2_bhh, gh);
        tg.o[1] = tg.o[0]; tg.o[2] = tg.o[0];
        gemm256_kernel<<<dim3(6, 79, 1), 256, GEMM_SMEM, s1>>>(tg, N_NODES, 256, 768);

        aggregate_split_kernel<<<2500, dim3(64, 4)>>>((const float4*)h2, ah, al,
                                                      rowptr, csr, 64);
        GTriple t;
        t.o[0] = mkop(ah, al, v2h + (long)i*768*256, v2l + (long)i*768*256, g2_bih, gi);
        t.o[1] = t.o[0]; t.o[2] = t.o[0];
        gemm256_kernel<<<dim3(6, 79, 1), 256, GEMM_SMEM>>>(t, N_NODES, 256, 768);

        cudaEventRecord(evJ, s1);
        cudaStreamWaitEvent(0, evJ, 0);
        gru_split_kernel<<<(N_NODES*64 + 255) / 256, 256>>>(
            (const float4*)gi, (const float4*)gh, (const float4*)h2, (float4*)h2, hh, hl, 256);
    }

    // pooling + FC (fused, last block runs FC)
    int pblocks = (N_NODES + 63) / 64;
    pool_fc_kernel<<<pblocks, 256>>>(h2, batch, pool, fc_w, fc_b, (float*)d_out, pblocks);
}

// round 17
// speedup vs baseline: 1.0332x; 1.0332x over previous
#include <cuda_runtime.h>
#include <cuda_bf16.h>
#include <math.h>
#include <stdint.h>

#define N_NODES 10000
#define N_EDGES 320000
#define N_GRAPHS 64

// ============================ device scratch =================================
__device__ __align__(16) float g_h1[N_NODES * 128];
__device__ __align__(16) float g_h2[N_NODES * 256];
__device__ __align__(16) float g_gi[N_NODES * 768];
__device__ __align__(16) float g_gh[N_NODES * 768];
__device__ int   g_rowptr[N_NODES + 1];
__device__ int   g_cnt[N_NODES];
__device__ int   g_cursor[N_NODES];
__device__ int   g_csr_src[N_EDGES];
__device__ unsigned g_pool[N_GRAPHS * 256];
__device__ int   g_e64, g_b64;
__device__ __align__(16) __nv_bfloat16 g_hh[N_NODES * 256], g_hl[N_NODES * 256];
__device__ __align__(16) __nv_bfloat16 g_ah[N_NODES * 256], g_al[N_NODES * 256];
__device__ __align__(16) __nv_bfloat16 g_w1uh[3*128*128], g_w1ul[3*128*128];
__device__ __align__(16) __nv_bfloat16 g_w2uh[3*256*256], g_w2ul[3*256*256];
__device__ __align__(16) __nv_bfloat16 g_i1h[384*128],  g_i1l[384*128];
__device__ __align__(16) __nv_bfloat16 g_r1h[384*128],  g_r1l[384*128];
__device__ __align__(16) __nv_bfloat16 g_i2h[768*256],  g_i2l[768*256];
__device__ __align__(16) __nv_bfloat16 g_r2h[768*256],  g_r2l[768*256];
__device__ __align__(16) __nv_bfloat16 g_v1h[3*384*128], g_v1l[3*384*128];
__device__ __align__(16) __nv_bfloat16 g_v2h[3*768*256], g_v2l[3*768*256];

// ============================ helpers ========================================
__device__ __forceinline__ unsigned f2ord(float f) {
    unsigned u = __float_as_uint(f);
    return (u & 0x80000000u) ? ~u : (u | 0x80000000u);
}
__device__ __forceinline__ float ord2f(unsigned u) {
    u = (u & 0x80000000u) ? (u & 0x7fffffffu) : ~u;
    return __uint_as_float(u);
}
__device__ __forceinline__ int load_idx(const void* p, long i, int is64) {
    return is64 ? (int)((const long long*)p)[i] : ((const int*)p)[i];
}
__device__ __forceinline__ void split1(float f, __nv_bfloat16& h, __nv_bfloat16& l) {
    h = __float2bfloat16(f);
    l = __float2bfloat16(f - __bfloat162float(h));
}

// ============================ prep ===========================================
__global__ void prep_kernel(const void* edge, const void* batch,
                            int* cnt, unsigned* pool) {
    int b = blockIdx.x, tid = threadIdx.x;
    int i = b * 256 + tid;
    if (i < N_NODES) cnt[i] = 0;
    if (i < N_GRAPHS * 256) pool[i] = f2ord(-3.402823466e38f);
    if (b == 64) {
        __shared__ int eo, bo;
        if (tid == 0) { eo = 0; bo = 0; }
        __syncthreads();
        const unsigned* we = (const unsigned*)edge;
        const unsigned* wb = (const unsigned*)batch;
        long ie = (long)tid * ((2L * N_EDGES) / 256);
        if (we[2 * ie + 1] != 0u) atomicOr(&eo, 1);
        long jb = (long)tid * (N_NODES / 256);
        if (wb[2 * jb + 1] != 0u) atomicOr(&bo, 1);
        __syncthreads();
        if (tid == 0) { g_e64 = !eo; g_b64 = !bo; }
    }
}

// =================== fused: hi/lo splits (z=0..6) + edge count (z=7) =========
struct SJob { const float* in; __nv_bfloat16* hi; __nv_bfloat16* lo; int n4; };
struct SJobs { SJob j[7]; };
__global__ void split_count_kernel(SJobs js, const void* edge, int* cnt) {
    if (blockIdx.z == 7) {
        int e = blockIdx.x * 256 + threadIdx.x;
        if (e < N_EDGES)
            atomicAdd(&cnt[load_idx(edge, (long)N_EDGES + e, g_e64)], 1);
        return;
    }
    SJob jb = js.j[blockIdx.z];
    int i = blockIdx.x * 256 + threadIdx.x;
    if (i >= jb.n4) return;
    float4 v = ((const float4*)jb.in)[i];
    __nv_bfloat16 h0, h1, h2, h3, l0, l1, l2, l3;
    split1(v.x, h0, l0); split1(v.y, h1, l1); split1(v.z, h2, l2); split1(v.w, h3, l3);
    ((__nv_bfloat162*)jb.hi)[2*i]   = __halves2bfloat162(h0, h1);
    ((__nv_bfloat162*)jb.hi)[2*i+1] = __halves2bfloat162(h2, h3);
    ((__nv_bfloat162*)jb.lo)[2*i]   = __halves2bfloat162(l0, l1);
    ((__nv_bfloat162*)jb.lo)[2*i+1] = __halves2bfloat162(l2, l3);
}

// ============================ CSR scan + fill ================================
__global__ void scan_kernel(const int* __restrict__ cnt, int* __restrict__ rowptr,
                            int* __restrict__ cursor, int n) {
    __shared__ int wsum[32];
    int tid = threadIdx.x, lane = tid & 31, wid = tid >> 5;
    int base = tid * 10;
    int v[10]; int s = 0;
    #pragma unroll
    for (int q = 0; q < 10; q++) {
        int i = base + q;
        int x = (i < n) ? cnt[i] : 0;
        s += x; v[q] = s;
    }
    int incl = s;
    #pragma unroll
    for (int o = 1; o < 32; o <<= 1) {
        int y = __shfl_up_sync(0xffffffffu, incl, o);
        if (lane >= o) incl += y;
    }
    if (lane == 31) wsum[wid] = incl;
    __syncthreads();
    if (wid == 0) {
        int t = wsum[lane];
        #pragma unroll
        for (int o = 1; o < 32; o <<= 1) {
            int y = __shfl_up_sync(0xffffffffu, t, o);
            if (lane >= o) t += y;
        }
        wsum[lane] = t;
    }
    __syncthreads();
    int excl = incl - s + (wid ? wsum[wid - 1] : 0);
    #pragma unroll
    for (int q = 0; q < 10; q++) {
        int i = base + q;
        if (i < n) {
            rowptr[i + 1] = excl + v[q];
            cursor[i] = excl + (q ? v[q - 1] : 0);
        }
    }
    if (tid == 0) rowptr[0] = 0;
}
__global__ void fill_kernel(const void* edge, int* cursor, int* csr_src) {
    int e = blockIdx.x * blockDim.x + threadIdx.x;
    if (e >= N_EDGES) return;
    int is64 = g_e64;
    int src = load_idx(edge, e, is64);
    int dst = load_idx(edge, (long)N_EDGES + e, is64);
    csr_src[atomicAdd(&cursor[dst], 1)] = src;
}

// ============================ HMMA GEMM core (128x128, 8 warps 32x64) ========
// 3 passes per 64-K block: (Ahi,Bhi), (Alo,Bhi), (Ahi,Blo) — Bhi/Ahi loaded
// ONCE per block into parity-indexed slots, Alo/Blo streamed.
// smem slots: 0=Ahi_even 1=Ahi_odd 2=Alo | 3=Bhi_even 4=Bhi_odd 5=Blo
struct GOp {
    const __nv_bfloat16 *Ah, *Al, *Bh, *Bl;
    const float* bias;
    float* C;
    __nv_bfloat16 *Chi, *Clo;
};
struct GTriple { GOp o[3]; };
#define TILE128 (128 * 72)
#define GEMM_SMEM (3 * 2 * TILE128 * 2)

__device__ __forceinline__ void ldsm_x4(uint32_t* r, uint32_t addr) {
    asm volatile("ldmatrix.sync.aligned.m8n8.x4.shared.b16 {%0,%1,%2,%3}, [%4];"
        : "=r"(r[0]), "=r"(r[1]), "=r"(r[2]), "=r"(r[3]) : "r"(addr));
}
__device__ __forceinline__ void mma_16816(float* d, const uint32_t* a,
                                          uint32_t b0, uint32_t b1) {
    asm volatile("mma.sync.aligned.m16n8k16.row.col.f32.bf16.bf16.f32 "
        "{%0,%1,%2,%3}, {%4,%5,%6,%7}, {%8,%9}, {%0,%1,%2,%3};"
        : "+f"(d[0]), "+f"(d[1]), "+f"(d[2]), "+f"(d[3])
        : "r"(a[0]), "r"(a[1]), "r"(a[2]), "r"(a[3]), "r"(b0), "r"(b1));
}
__device__ __forceinline__ void cp16(uint32_t dst, const void* src, bool pred) {
    int sz = pred ? 16 : 0;
    asm volatile("cp.async.cg.shared.global [%0], [%1], 16, %2;"
        :: "r"(dst), "l"(src), "r"(sz) : "memory");
}
__device__ __forceinline__ void gemm_issue(
    const GOp& o, int c, int nc, int tid, int row0, int col0,
    int Nrows, int K, uint32_t smu)
{
    if (c < nc) {
        int k0i = c / 3, p = c - k0i * 3;
        int k0 = k0i << 6;
        int par = k0i & 1;
        if (p == 0) {
            uint32_t bA = smu + (uint32_t)(par * TILE128) * 2;
            uint32_t bB = smu + (uint32_t)((3 + par) * TILE128) * 2;
            #pragma unroll
            for (int q = 0; q < 4; q++) {
                int idx = q * 256 + tid;
                int row = idx >> 3, seg = (idx & 7) << 3;
                int gr = row0 + row;
                long grc = (gr < Nrows) ? gr : 0;
                cp16(bA + (uint32_t)(row * 72 + seg) * 2,
                     o.Ah + grc * K + k0 + seg, gr < Nrows);
                cp16(bB + (uint32_t)(row * 72 + seg) * 2,
                     o.Bh + (long)(col0 + row) * K + k0 + seg, true);
            }
        } else if (p == 1) {
            uint32_t bA = smu + (uint32_t)(2 * TILE128) * 2;
            #pragma unroll
            for (int q = 0; q < 4; q++) {
                int idx = q * 256 + tid;
                int row = idx >> 3, seg = (idx & 7) << 3;
                int gr = row0 + row;
                long grc = (gr < Nrows) ? gr : 0;
                cp16(bA + (uint32_t)(row * 72 + seg) * 2,
                     o.Al + grc * K + k0 + seg, gr < Nrows);
            }
        } else {
            uint32_t bB = smu + (uint32_t)(5 * TILE128) * 2;
            #pragma unroll
            for (int q = 0; q < 4; q++) {
                int idx = q * 256 + tid;
                int row = idx >> 3, seg = (idx & 7) << 3;
                cp16(bB + (uint32_t)(row * 72 + seg) * 2,
                     o.Bl + (long)(col0 + row) * K + k0 + seg, true);
            }
        }
    }
    asm volatile("cp.async.commit_group;" ::: "memory");
}

__device__ void gemm_body256(const GOp& o, int row0, int col0,
                             int Nrows, int K, int Ncols)
{
    extern __shared__ __nv_bfloat16 smg[];
    uint32_t smu = (uint32_t)__cvta_generic_to_shared(smg);
    int tid = threadIdx.x, lane = tid & 31, wid = tid >> 5;
    int wm = (wid & 3) * 32, wn = (wid >> 2) * 64;

    float acc[2][8][4];
    #pragma unroll
    for (int i = 0; i < 2; i++)
        #pragma unroll
        for (int j = 0; j < 8; j++)
            #pragma unroll
            for (int q = 0; q < 4; q++) acc[i][j][q] = 0.f;

    int nc = 3 * (K >> 6);
    gemm_issue(o, 0, nc, tid, row0, col0, Nrows, K, smu);
    gemm_issue(o, 1, nc, tid, row0, col0, Nrows, K, smu);

    for (int c = 0; c < nc; c++) {
        asm volatile("cp.async.wait_group 1;" ::: "memory");
        __syncthreads();
        gemm_issue(o, c + 2, nc, tid, row0, col0, Nrows, K, smu);

        int k0i = c / 3, p = c - k0i * 3;
        int par = k0i & 1;
        int slotA = (p == 1) ? 2 : par;
        int slotB = (p == 2) ? 5 : (3 + par);
        uint32_t bA = smu + (uint32_t)(slotA * TILE128) * 2;
        uint32_t bB = smu + (uint32_t)(slotB * TILE128) * 2;
        #pragma unroll
        for (int ks = 0; ks < 4; ks++) {
            uint32_t af[2][4], bf[4][4];
            #pragma unroll
            for (int ti = 0; ti < 2; ti++) {
                int row = wm + ti * 16 + (lane & 15);
                int col = ks * 16 + (lane >> 4) * 8;
                ldsm_x4(af[ti], bA + (uint32_t)(row * 72 + col) * 2);
            }
            #pragma unroll
            for (int g = 0; g < 4; g++) {
                int row = wn + g * 16 + (lane & 7) + ((lane >> 4) << 3);
                int col = ks * 16 + ((lane >> 3) & 1) * 8;
                ldsm_x4(bf[g], bB + (uint32_t)(row * 72 + col) * 2);
            }
            #pragma unroll
            for (int ti = 0; ti < 2; ti++)
                #pragma unroll
                for (int g = 0; g < 4; g++) {
                    mma_16816(acc[ti][g*2],     af[ti], bf[g][0], bf[g][1]);
                    mma_16816(acc[ti][g*2 + 1], af[ti], bf[g][2], bf[g][3]);
                }
        }
    }

    #pragma unroll
    for (int ti = 0; ti < 2; ti++) {
        int rb = row0 + wm + ti * 16 + (lane >> 2);
        #pragma unroll
        for (int g = 0; g < 8; g++) {
            int col = col0 + wn + g * 8 + (lane & 3) * 2;
            float bx = 0.f, by = 0.f;
            if (o.bias) { bx = o.bias[col]; by = o.bias[col + 1]; }
            float v0 = acc[ti][g][0] + bx, v1 = acc[ti][g][1] + by;
            float v2 = acc[ti][g][2] + bx, v3 = acc[ti][g][3] + by;
            if (o.Chi) {
                __nv_bfloat16 h0, h1, l0, l1;
                if (rb < Nrows) {
                    split1(v0, h0, l0); split1(v1, h1, l1);
                    *(__nv_bfloat162*)&o.Chi[(long)rb * Ncols + col] = __halves2bfloat162(h0, h1);
                    *(__nv_bfloat162*)&o.Clo[(long)rb * Ncols + col] = __halves2bfloat162(l0, l1);
                }
                if (rb + 8 < Nrows) {
                    split1(v2, h0, l0); split1(v3, h1, l1);
                    *(__nv_bfloat162*)&o.Chi[(long)(rb+8) * Ncols + col] = __halves2bfloat162(h0, h1);
                    *(__nv_bfloat162*)&o.Clo[(long)(rb+8) * Ncols + col] = __halves2bfloat162(l0, l1);
                }
            } else {
                if (rb < Nrows)
                    *(float2*)&o.C[(long)rb * Ncols + col] = make_float2(v0, v1);
                if (rb + 8 < Nrows)
                    *(float2*)&o.C[(long)(rb + 8) * Ncols + col] = make_float2(v2, v3);
            }
        }
    }
}

__global__ __launch_bounds__(256, 2) void gemm256_kernel(
    GTriple t, int Nrows, int K, int Ncols)
{
    gemm_body256(t.o[blockIdx.z], blockIdx.y * 128, blockIdx.x * 128, Nrows, K, Ncols);
}

// merged V1+V2 precompute: grid dim3(2,6,6); z<3 -> V1 (1x3 tiles), z>=3 -> V2
__global__ __launch_bounds__(256, 2) void gemm_v_kernel(GTriple t1, GTriple t2)
{
    if (blockIdx.z < 3) {
        if (blockIdx.x >= 1 || blockIdx.y >= 3) return;
        gemm_body256(t1.o[blockIdx.z], blockIdx.y * 128, blockIdx.x * 128, 384, 128, 128);
    } else {
        gemm_body256(t2.o[blockIdx.z - 3], blockIdx.y * 128, blockIdx.x * 128, 768, 256, 256);
    }
}

// ============================ aggregation (fp32 gather, fused split) =========
__global__ void aggregate_split_kernel(const float4* __restrict__ h4,
                                       __nv_bfloat16* __restrict__ ahi,
                                       __nv_bfloat16* __restrict__ alo,
                                       const int* __restrict__ rowptr,
                                       const int* __restrict__ csr, int C4)
{
    int n = blockIdx.x * blockDim.y + threadIdx.y;
    if (n >= N_NODES) return;
    int f = threadIdx.x;
    int beg = rowptr[n], end = rowptr[n + 1];
    float4 a0 = make_float4(0.f,0.f,0.f,0.f), a1 = a0, a2 = a0, a3 = a0;
    int j = beg;
    for (; j + 4 <= end; j += 4) {
        int s0 = csr[j], s1 = csr[j+1], s2 = csr[j+2], s3 = csr[j+3];
        float4 v0 = h4[(long)s0 * C4 + f];
        float4 v1 = h4[(long)s1 * C4 + f];
        float4 v2 = h4[(long)s2 * C4 + f];
        float4 v3 = h4[(long)s3 * C4 + f];
        a0.x += v0.x; a0.y += v0.y; a0.z += v0.z; a0.w += v0.w;
        a1.x += v1.x; a1.y += v1.y; a1.z += v1.z; a1.w += v1.w;
        a2.x += v2.x; a2.y += v2.y; a2.z += v2.z; a2.w += v2.w;
        a3.x += v3.x; a3.y += v3.y; a3.z += v3.z; a3.w += v3.w;
    }
    for (; j < end; j++) {
        int s = csr[j];
        float4 v = h4[(long)s * C4 + f];
        a0.x += v.x; a0.y += v.y; a0.z += v.z; a0.w += v.w;
    }
    float4 acc;
    acc.x = (a0.x + a1.x) + (a2.x + a3.x);
    acc.y = (a0.y + a1.y) + (a2.y + a3.y);
    acc.z = (a0.z + a1.z) + (a2.z + a3.z);
    acc.w = (a0.w + a1.w) + (a2.w + a3.w);
    long o = ((long)n * C4 + f) * 2;
    __nv_bfloat16 h0,h1,h2,h3,l0,l1,l2,l3;
    split1(acc.x, h0, l0); split1(acc.y, h1, l1);
    split1(acc.z, h2, l2); split1(acc.w, h3, l3);
    ((__nv_bfloat162*)ahi)[o]   = __halves2bfloat162(h0, h1);
    ((__nv_bfloat162*)ahi)[o+1] = __halves2bfloat162(h2, h3);
    ((__nv_bfloat162*)alo)[o]   = __halves2bfloat162(l0, l1);
    ((__nv_bfloat162*)alo)[o+1] = __halves2bfloat162(l2, l3);
}

// ============================ GRU (float4, fused split) ======================
__global__ void gru_split_kernel(const float4* __restrict__ gi4, const float4* __restrict__ gh4,
                                 const float4* __restrict__ h4, float4* __restrict__ hout4,
                                 __nv_bfloat16* __restrict__ hhi, __nv_bfloat16* __restrict__ hlo,
                                 int C)
{
    int i = blockIdx.x * blockDim.x + threadIdx.x;
    int C4 = C >> 2;
    if (i >= N_NODES * C4) return;
    int n = i / C4, f4 = i % C4;
    const float4* gir = gi4 + (long)n * 3 * C4;
    const float4* ghr = gh4 + (long)n * 3 * C4;
    float4 ir = gir[f4], iz = gir[C4 + f4], in_ = gir[2 * C4 + f4];
    float4 hr = ghr[f4], hz = ghr[C4 + f4], hn  = ghr[2 * C4 + f4];
    float4 hv = h4[i];
    float o[4];
    {
        float r0 = 1.f / (1.f + expf(-(ir.x + hr.x)));
        float z0 = 1.f / (1.f + expf(-(iz.x + hz.x)));
        o[0] = (1.f - z0) * tanhf(in_.x + r0 * hn.x) + z0 * hv.x;
        float r1 = 1.f / (1.f + expf(-(ir.y + hr.y)));
        float z1 = 1.f / (1.f + expf(-(iz.y + hz.y)));
        o[1] = (1.f - z1) * tanhf(in_.y + r1 * hn.y) + z1 * hv.y;
        float r2 = 1.f / (1.f + expf(-(ir.z + hr.z)));
        float z2 = 1.f / (1.f + expf(-(iz.z + hz.z)));
        o[2] = (1.f - z2) * tanhf(in_.z + r2 * hn.z) + z2 * hv.z;
        float r3 = 1.f / (1.f + expf(-(ir.w + hr.w)));
        float z3 = 1.f / (1.f + expf(-(iz.w + hz.w)));
        o[3] = (1.f - z3) * tanhf(in_.w + r3 * hn.w) + z3 * hv.w;
    }
    hout4[i] = make_float4(o[0], o[1], o[2], o[3]);
    __nv_bfloat16 bh0,bh1,bh2,bh3,bl0,bl1,bl2,bl3;
    split1(o[0], bh0, bl0); split1(o[1], bh1, bl1);
    split1(o[2], bh2, bl2); split1(o[3], bh3, bl3);
    ((__nv_bfloat162*)hhi)[2*i]   = __halves2bfloat162(bh0, bh1);
    ((__nv_bfloat162*)hhi)[2*i+1] = __halves2bfloat162(bh2, bh3);
    ((__nv_bfloat162*)hlo)[2*i]   = __halves2bfloat162(bl0, bl1);
    ((__nv_bfloat162*)hlo)[2*i+1] = __halves2bfloat162(bl2, bl3);
}

// Final stage-1 GRU: fuses relu + pad 128->256 (writes 256-wide h2 + hi/lo).
__global__ void gru_pad_relu_split_kernel(
    const float4* __restrict__ gi4, const float4* __restrict__ gh4,
    const float4* __restrict__ h4, float4* __restrict__ h2_4,
    __nv_bfloat16* __restrict__ hhi, __nv_bfloat16* __restrict__ hlo)
{
    int i = blockIdx.x * blockDim.x + threadIdx.x;        // over N_NODES*64
    if (i >= N_NODES * 64) return;
    int n = i >> 6, f4 = i & 63;
    float o[4] = {0.f, 0.f, 0.f, 0.f};
    if (f4 < 32) {
        const float4* gir = gi4 + (long)n * 96;
        const float4* ghr = gh4 + (long)n * 96;
        float4 ir = gir[f4], iz = gir[32 + f4], in_ = gir[64 + f4];
        float4 hr = ghr[f4], hz = ghr[32 + f4], hn  = ghr[64 + f4];
        float4 hv = h4[n * 32 + f4];
        float r0 = 1.f / (1.f + expf(-(ir.x + hr.x)));
        float z0 = 1.f / (1.f + expf(-(iz.x + hz.x)));
        o[0] = fmaxf((1.f - z0) * tanhf(in_.x + r0 * hn.x) + z0 * hv.x, 0.f);
        float r1 = 1.f / (1.f + expf(-(ir.y + hr.y)));
        float z1 = 1.f / (1.f + expf(-(iz.y + hz.y)));
        o[1] = fmaxf((1.f - z1) * tanhf(in_.y + r1 * hn.y) + z1 * hv.y, 0.f);
        float r2 = 1.f / (1.f + expf(-(ir.z + hr.z)));
        float z2 = 1.f / (1.f + expf(-(iz.z + hz.z)));
        o[2] = fmaxf((1.f - z2) * tanhf(in_.z + r2 * hn.z) + z2 * hv.z, 0.f);
        float r3 = 1.f / (1.f + expf(-(ir.w + hr.w)));
        float z3 = 1.f / (1.f + expf(-(iz.w + hz.w)));
        o[3] = fmaxf((1.f - z3) * tanhf(in_.w + r3 * hn.w) + z3 * hv.w, 0.f);
    }
    h2_4[i] = make_float4(o[0], o[1], o[2], o[3]);
    __nv_bfloat16 bh0,bh1,bh2,bh3,bl0,bl1,bl2,bl3;
    split1(o[0], bh0, bl0); split1(o[1], bh1, bl1);
    split1(o[2], bh2, bl2); split1(o[3], bh3, bl3);
    ((__nv_bfloat162*)hhi)[2*i]   = __halves2bfloat162(bh0, bh1);
    ((__nv_bfloat162*)hhi)[2*i+1] = __halves2bfloat162(bh2, bh3);
    ((__nv_bfloat162*)hlo)[2*i]   = __halves2bfloat162(bl0, bl1);
    ((__nv_bfloat162*)hlo)[2*i+1] = __halves2bfloat162(bl2, bl3);
}

// ============================ pooling + FC ===================================
__global__ void pool_max2_kernel(const float* __restrict__ h, const void* batch,
                                 unsigned* __restrict__ pool) {
    int f = threadIdx.x;                  // 0..255
    int n0 = blockIdx.x * 64;
    int b64 = g_b64;
    int gcur = -1;
    float m = -3.402823466e38f;
    #pragma unroll 4
    for (int k = 0; k < 64; k++) {
        int n = n0 + k;
        if (n >= N_NODES) break;
        int g = load_idx(batch, n, b64);
        if (g != gcur) {
            if (gcur >= 0) atomicMax(&pool[gcur * 256 + f], f2ord(m));
            gcur = g;
            m = -3.402823466e38f;
        }
        m = fmaxf(m, h[(long)n * 256 + f]);
    }
    if (gcur >= 0) atomicMax(&pool[gcur * 256 + f], f2ord(m));
}
__global__ void fc_kernel(const unsigned* __restrict__ pool, const float* __restrict__ w,
                          const float* __restrict__ b, float* __restrict__ out) {
    int t = threadIdx.x;
    if (t >= N_GRAPHS * 6) return;
    int g = t / 6, j = t % 6;
    float s = b[j];
    for (int k = 0; k < 256; k++)
        s += ord2f(pool[g * 256 + k]) * w[j * 256 + k];
    out[t] = s;
}

// ============================ launch =========================================
static inline GOp mkop(const __nv_bfloat16* Ah, const __nv_bfloat16* Al,
                       const __nv_bfloat16* Bh, const __nv_bfloat16* Bl,
                       const float* bias, float* C,
                       __nv_bfloat16* Chi = nullptr, __nv_bfloat16* Clo = nullptr) {
    GOp o; o.Ah = Ah; o.Al = Al; o.Bh = Bh; o.Bl = Bl;
    o.bias = bias; o.C = C; o.Chi = Chi; o.Clo = Clo; return o;
}

extern "C" void kernel_launch(void* const* d_in, const int* in_sizes, int n_in,
                              void* d_out, int out_size)
{
    const float* x       = (const float*)d_in[0];
    const void*  edge    = d_in[1];
    const void*  batch   = d_in[2];
    const float* w1      = (const float*)d_in[3];
    const float* g1_wih  = (const float*)d_in[4];
    const float* g1_whh  = (const float*)d_in[5];
    const float* g1_bih  = (const float*)d_in[6];
    const float* g1_bhh  = (const float*)d_in[7];
    const float* w2      = (const float*)d_in[8];
    const float* g2_wih  = (const float*)d_in[9];
    const float* g2_whh  = (const float*)d_in[10];
    const float* g2_bih  = (const float*)d_in[11];
    const float* g2_bhh  = (const float*)d_in[12];
    const float* fc_w    = (const float*)d_in[13];
    const float* fc_b    = (const float*)d_in[14];

    cudaFuncSetAttribute(gemm256_kernel, cudaFuncAttributeMaxDynamicSharedMemorySize,
                         GEMM_SMEM);
    cudaFuncSetAttribute(gemm_v_kernel, cudaFuncAttributeMaxDynamicSharedMemorySize,
                         GEMM_SMEM);

    static cudaStream_t s1 = nullptr;
    static cudaEvent_t evF = nullptr, evJ = nullptr;
    if (!s1) {
        cudaStreamCreateWithFlags(&s1, cudaStreamNonBlocking);
        cudaEventCreateWithFlags(&evF, cudaEventDisableTiming);
        cudaEventCreateWithFlags(&evJ, cudaEventDisableTiming);
    }

    float *h1, *h2, *gi, *gh;
    int *rowptr, *cnt, *cursor, *csr;
    unsigned* pool;
    __nv_bfloat16 *hh, *hl, *ah, *al;
    __nv_bfloat16 *w1uh, *w1ul, *w2uh, *w2ul;
    __nv_bfloat16 *i1h, *i1l, *r1h, *r1l, *i2h, *i2l, *r2h, *r2l;
    __nv_bfloat16 *v1h, *v1l, *v2h, *v2l;
    cudaGetSymbolAddress((void**)&h1, g_h1);   cudaGetSymbolAddress((void**)&h2, g_h2);
    cudaGetSymbolAddress((void**)&gi, g_gi);   cudaGetSymbolAddress((void**)&gh, g_gh);
    cudaGetSymbolAddress((void**)&rowptr, g_rowptr); cudaGetSymbolAddress((void**)&cnt, g_cnt);
    cudaGetSymbolAddress((void**)&cursor, g_cursor); cudaGetSymbolAddress((void**)&csr, g_csr_src);
    cudaGetSymbolAddress((void**)&pool, g_pool);
    cudaGetSymbolAddress((void**)&hh, g_hh);   cudaGetSymbolAddress((void**)&hl, g_hl);
    cudaGetSymbolAddress((void**)&ah, g_ah);   cudaGetSymbolAddress((void**)&al, g_al);
    cudaGetSymbolAddress((void**)&w1uh, g_w1uh); cudaGetSymbolAddress((void**)&w1ul, g_w1ul);
    cudaGetSymbolAddress((void**)&w2uh, g_w2uh); cudaGetSymbolAddress((void**)&w2ul, g_w2ul);
    cudaGetSymbolAddress((void**)&i1h, g_i1h); cudaGetSymbolAddress((void**)&i1l, g_i1l);
    cudaGetSymbolAddress((void**)&r1h, g_r1h); cudaGetSymbolAddress((void**)&r1l, g_r1l);
    cudaGetSymbolAddress((void**)&i2h, g_i2h); cudaGetSymbolAddress((void**)&i2l, g_i2l);
    cudaGetSymbolAddress((void**)&r2h, g_r2h); cudaGetSymbolAddress((void**)&r2l, g_r2l);
    cudaGetSymbolAddress((void**)&v1h, g_v1h); cudaGetSymbolAddress((void**)&v1l, g_v1l);
    cudaGetSymbolAddress((void**)&v2h, g_v2h); cudaGetSymbolAddress((void**)&v2l, g_v2l);

    // ---- prologue ----
    prep_kernel<<<65, 256>>>(edge, batch, cnt, pool);

    SJobs js;
    js.j[0] = { x,      hh,   hl,   N_NODES*128/4 };
    js.j[1] = { w1,     w1uh, w1ul, 3*128*128/4 };
    js.j[2] = { w2,     w2uh, w2ul, 3*256*256/4 };
    js.j[3] = { g1_wih, i1h,  i1l,  384*128/4 };
    js.j[4] = { g1_whh, r1h,  r1l,  384*128/4 };
    js.j[5] = { g2_wih, i2h,  i2l,  768*256/4 };
    js.j[6] = { g2_whh, r2h,  r2l,  768*256/4 };
    split_count_kernel<<<dim3(1250, 1, 8), 256>>>(js, edge, cnt);

    // fork: side stream does V precompute (merged) + layer-0 gh
    cudaEventRecord(evF, 0);
    cudaStreamWaitEvent(s1, evF, 0);
    {
        GTriple t1, t2;
        for (int q = 0; q < 3; q++) {
            t1.o[q] = mkop(i1h, i1l, w1uh + (long)q*128*128, w1ul + (long)q*128*128,
                           nullptr, nullptr, v1h + (long)q*384*128, v1l + (long)q*384*128);
            t2.o[q] = mkop(i2h, i2l, w2uh + (long)q*256*256, w2ul + (long)q*256*256,
                           nullptr, nullptr, v2h + (long)q*768*256, v2l + (long)q*768*256);
        }
        gemm_v_kernel<<<dim3(2, 6, 6), 256, GEMM_SMEM, s1>>>(t1, t2);
    }
    {
        GTriple t;
        t.o[0] = mkop(hh, hl, r1h, r1l, g1_bhh, gh);
        t.o[1] = t.o[0]; t.o[2] = t.o[0];
        gemm256_kernel<<<dim3(3, 79, 1), 256, GEMM_SMEM, s1>>>(t, N_NODES, 128, 384);
    }

    // main stream: CSR build + layer-0 aggregation (fp32 gather of x)
    scan_kernel<<<1, 1024>>>(cnt, rowptr, cursor, N_NODES);
    fill_kernel<<<(N_EDGES + 255) / 256, 256>>>(edge, cursor, csr);
    aggregate_split_kernel<<<1250, dim3(32, 8)>>>((const float4*)x, ah, al, rowptr, csr, 32);

    // ---- stage 1: C = 128 ----
    for (int i = 0; i < 3; i++) {
        const float* h = (i == 0) ? x : h1;
        if (i > 0) {
            cudaEventRecord(evF, 0);
            cudaStreamWaitEvent(s1, evF, 0);
            GTriple tg;
            tg.o[0] = mkop(hh, hl, r1h, r1l, g1_bhh, gh);
            tg.o[1] = tg.o[0]; tg.o[2] = tg.o[0];
            gemm256_kernel<<<dim3(3, 79, 1), 256, GEMM_SMEM, s1>>>(tg, N_NODES, 128, 384);
            aggregate_split_kernel<<<1250, dim3(32, 8)>>>((const float4*)h, ah, al,
                                                          rowptr, csr, 32);
        }
        cudaEventRecord(evJ, s1);
        cudaStreamWaitEvent(0, evJ, 0);

        GTriple t;
        t.o[0] = mkop(ah, al, v1h + (long)i*384*128, v1l + (long)i*384*128, g1_bih, gi);
        t.o[1] = t.o[0]; t.o[2] = t.o[0];
        gemm256_kernel<<<dim3(3, 79, 1), 256, GEMM_SMEM>>>(t, N_NODES, 128, 384);
        if (i < 2) {
            gru_split_kernel<<<(N_NODES*32 + 255) / 256, 256>>>(
                (const float4*)gi, (const float4*)gh, (const float4*)h, (float4*)h1,
                hh, hl, 128);
        } else {
            gru_pad_relu_split_kernel<<<(N_NODES*64 + 255) / 256, 256>>>(
                (const float4*)gi, (const float4*)gh, (const float4*)h, (float4*)h2,
                hh, hl);
        }
    }

    // ---- stage 2: C = 256 ----
    for (int i = 0; i < 3; i++) {
        cudaEventRecord(evF, 0);
        cudaStreamWaitEvent(s1, evF, 0);
        GTriple tg;
        tg.o[0] = mkop(hh, hl, r2h, r2l, g2_bhh, gh);
        tg.o[1] = tg.o[0]; tg.o[2] = tg.o[0];
        gemm256_kernel<<<dim3(6, 79, 1), 256, GEMM_SMEM, s1>>>(tg, N_NODES, 256, 768);

        aggregate_split_kernel<<<2500, dim3(64, 4)>>>((const float4*)h2, ah, al,
                                                      rowptr, csr, 64);
        GTriple t;
        t.o[0] = mkop(ah, al, v2h + (long)i*768*256, v2l + (long)i*768*256, g2_bih, gi);
        t.o[1] = t.o[0]; t.o[2] = t.o[0];
        gemm256_kernel<<<dim3(6, 79, 1), 256, GEMM_SMEM>>>(t, N_NODES, 256, 768);

        cudaEventRecord(evJ, s1);
        cudaStreamWaitEvent(0, evJ, 0);
        gru_split_kernel<<<(N_NODES*64 + 255) / 256, 256>>>(
            (const float4*)gi, (const float4*)gh, (const float4*)h2, (float4*)h2, hh, hl, 256);
    }

    // pooling + FC
    pool_max2_kernel<<<(N_NODES + 63) / 64, 256>>>(h2, batch, pool);
    fc_kernel<<<1, N_GRAPHS * 6>>>(pool, fc_w, fc_b, (float*)d_out);
}